// round 2
// baseline (speedup 1.0000x reference)
#include <cuda_runtime.h>
#include <math.h>

#define BB   8
#define LL   2000
#define EE   300
#define NLB  8922
#define LWW  10
#define FF   200
#define KK   10
#define HH   200
#define FEAT 500
#define LP   1991     // L - K + 1
#define CT   32       // conv l-tile
#define NT   16       // labels per attention block

// ---------------- scratch (static device allocations; no cudaMalloc) ----------
__device__ float g_avg[NLB * EE];          // 10.7 MB
__device__ float g_gemb[NLB * FEAT];       // 17.8 MB
__device__ float g_c[(size_t)BB * LP * FF];        // 12.7 MB  [B][Lp][F]
__device__ float g_pjT[(size_t)BB * EE * LP];      // 19.1 MB  [B][E][Lp]
__device__ float g_losspart[64];

// ---------------- 1. average label embedding ----------------------------------
__global__ void k_avg(const float* __restrict__ we, const int* __restrict__ lidx,
                      const float* __restrict__ lmask) {
    int n = blockIdx.x;
    int t = threadIdx.x;
    __shared__ int   idx_s[LWW];
    __shared__ float m_s[LWW];
    __shared__ float inv;
    if (t < LWW) { idx_s[t] = lidx[n * LWW + t]; m_s[t] = lmask[n * LWW + t]; }
    __syncthreads();
    if (t == 0) {
        float s = 0.f;
        for (int w = 0; w < LWW; w++) s += m_s[w];
        inv = 1.f / s;
    }
    __syncthreads();
    if (t < EE) {
        float s = 0.f;
        for (int w = 0; w < LWW; w++)
            s += we[(size_t)idx_s[w] * EE + t] * m_s[w];
        g_avg[(size_t)n * EE + t] = s * inv;
    }
}

// ---------------- 2. sparse graph aggregate + Wg + concat ---------------------
__global__ void k_graph(const float* __restrict__ adj, const float* __restrict__ nn,
                        const float* __restrict__ Wg, const float* __restrict__ bg) {
    int n = blockIdx.x;
    int t = threadIdx.x;
    __shared__ int   list[256];
    __shared__ int   cnt;
    __shared__ float agg_s[EE];
    if (t == 0) cnt = 0;
    __syncthreads();
    for (int j = t; j < NLB; j += blockDim.x) {
        if (adj[(size_t)n * NLB + j] != 0.f) {
            int p = atomicAdd(&cnt, 1);
            if (p < 256) list[p] = j;
        }
    }
    __syncthreads();
    int m = cnt < 256 ? cnt : 256;
    if (t == 0) {            // deterministic ascending order
        for (int i = 1; i < m; i++) {
            int v = list[i], j = i - 1;
            while (j >= 0 && list[j] > v) { list[j + 1] = list[j]; j--; }
            list[j + 1] = v;
        }
    }
    __syncthreads();
    float invd = 1.f / nn[n];
    if (t < EE) {
        float s = 0.f;
        for (int i = 0; i < m; i++) s += g_avg[(size_t)list[i] * EE + t];
        agg_s[t] = s * invd;
        g_gemb[(size_t)n * FEAT + t] = g_avg[(size_t)n * EE + t];
    }
    __syncthreads();
    if (t < HH) {
        float s = bg[t];
        for (int e = 0; e < EE; e++) s += agg_s[e] * Wg[e * HH + t];
        g_gemb[(size_t)n * FEAT + EE + t] = fmaxf(s, 0.f);
    }
}

// ---------------- 3. document conv (im2col-free, reg-tiled) -------------------
__global__ void k_conv(const int* __restrict__ x, const float* __restrict__ mask,
                       const float* __restrict__ we, const float* __restrict__ Wc,
                       const float* __restrict__ bc) {
    extern __shared__ float xe_s[];            // (CT+KK-1)*EE = 41*300 floats
    const int TW = CT + KK - 1;                // 41
    int b  = blockIdx.y;
    int l0 = blockIdx.x * CT;
    int t  = threadIdx.x;                      // 224 threads

    for (int i = t; i < TW * EE; i += blockDim.x) {
        int tt = i / EE, e = i % EE;
        int gt = l0 + tt;
        float v = 0.f;
        if (gt < LL) v = we[(size_t)x[b * LL + gt] * EE + e] * mask[b * LL + gt];
        xe_s[i] = v;
    }
    __syncthreads();

    int f = t;
    if (f < FF) {
        float acc[CT];
        float bcv = bc[f];
        #pragma unroll
        for (int l = 0; l < CT; l++) acc[l] = bcv;
        const float* wrow = Wc + (size_t)f * EE * KK;
        for (int e = 0; e < EE; e++) {
            float wcr[KK];
            #pragma unroll
            for (int k = 0; k < KK; k++) wcr[k] = wrow[e * KK + k];
            #pragma unroll
            for (int tt = 0; tt < TW; tt++) {
                float xv = xe_s[tt * EE + e];
                #pragma unroll
                for (int k = 0; k < KK; k++) {
                    int l = tt - k;
                    if (l >= 0 && l < CT) acc[l] += xv * wcr[k];
                }
            }
        }
        #pragma unroll
        for (int l = 0; l < CT; l++) {
            int gl = l0 + l;
            if (gl < LP)
                g_c[((size_t)b * LP + gl) * FF + f] = fmaxf(acc[l], 0.f);
        }
    }
}

// ---------------- 4. pj = tanh(c @ Wp + bp), stored transposed [B][E][Lp] ----
__global__ void k_pj(const float* __restrict__ Wp, const float* __restrict__ bp) {
    __shared__ float c_s[CT * 201];            // pad 201 -> conflict-free
    int b  = blockIdx.y;
    int l0 = blockIdx.x * CT;
    int t  = threadIdx.x;                      // 256
    for (int i = t; i < CT * FF; i += 256) {
        int l = i / FF, f = i % FF;
        int gl = l0 + l;
        c_s[l * 201 + f] = (gl < LP) ? g_c[((size_t)b * LP + gl) * FF + f] : 0.f;
    }
    __syncthreads();
    int l  = t & 31;
    int eg = t >> 5;                           // 8 e-groups
    int gl = l0 + l;
    for (int e = eg; e < EE; e += 8) {
        float s = bp[e];
        for (int f = 0; f < FF; f++) s += c_s[l * 201 + f] * Wp[f * EE + e];
        if (gl < LP)
            g_pjT[((size_t)b * EE + e) * LP + gl] = tanhf(s);
    }
}

// ---------------- 5. fused attention + proj + logits --------------------------
// smem: scores[LP][NT], avgT[EE][NT], o_s[FF][NT], rowsum[NT], wpart[NT][8]
#define ATTN_SMEM_FLOATS (LP * NT + EE * NT + FF * NT + NT + NT * 8)

__global__ void k_attn(const float* __restrict__ Wo, const float* __restrict__ bo,
                       float* __restrict__ logits_out) {
    extern __shared__ float sm[];
    float* scores = sm;                   // LP*NT
    float* avgT   = scores + LP * NT;     // EE*NT  (layout [e][n] -> float4 over n)
    float* o_s    = avgT + EE * NT;       // FF*NT  (layout [f][n])
    float* rowsum = o_s + FF * NT;        // NT
    float* wpart  = rowsum + NT;          // NT*8

    int b  = blockIdx.y;
    int n0 = blockIdx.x * NT;
    int t  = threadIdx.x;                 // 256
    int w  = t >> 5, lane = t & 31;

    for (int i = t; i < EE * NT; i += 256) {
        int n = i & (NT - 1), e = i >> 4;
        int gn = n0 + n;
        avgT[i] = (gn < NLB) ? g_avg[(size_t)gn * EE + e] : 0.f;
    }
    __syncthreads();

    // ---- phase 1: scores[n][l] = sum_e avg[n][e] * pjT[b][e][l] --------------
    const float* pjb = g_pjT + (size_t)b * EE * LP;
    for (int l = t; l < LP; l += 512) {
        float a0[NT], a1[NT];
        #pragma unroll
        for (int n = 0; n < NT; n++) { a0[n] = 0.f; a1[n] = 0.f; }
        int l1 = l + 256;
        bool v1 = (l1 < LP);
        for (int e = 0; e < EE; e++) {
            float p0 = pjb[(size_t)e * LP + l];
            float p1 = v1 ? pjb[(size_t)e * LP + l1] : 0.f;
            const float4* av = (const float4*)(avgT + e * NT);
            #pragma unroll
            for (int q = 0; q < 4; q++) {
                float4 a = av[q];
                a0[q*4+0] += p0 * a.x; a0[q*4+1] += p0 * a.y;
                a0[q*4+2] += p0 * a.z; a0[q*4+3] += p0 * a.w;
                a1[q*4+0] += p1 * a.x; a1[q*4+1] += p1 * a.y;
                a1[q*4+2] += p1 * a.z; a1[q*4+3] += p1 * a.w;
            }
        }
        float4* sc0 = (float4*)(scores + l * NT);
        #pragma unroll
        for (int q = 0; q < 4; q++)
            sc0[q] = make_float4(a0[q*4], a0[q*4+1], a0[q*4+2], a0[q*4+3]);
        if (v1) {
            float4* sc1 = (float4*)(scores + l1 * NT);
            #pragma unroll
            for (int q = 0; q < 4; q++)
                sc1[q] = make_float4(a1[q*4], a1[q*4+1], a1[q*4+2], a1[q*4+3]);
        }
    }
    __syncthreads();

    // ---- phase 2: softmax over l (exact, max-subtracted) ---------------------
    for (int n = w * 2; n < w * 2 + 2; n++) {
        float m = -1e30f;
        for (int l = lane; l < LP; l += 32) m = fmaxf(m, scores[l * NT + n]);
        #pragma unroll
        for (int o = 16; o; o >>= 1) m = fmaxf(m, __shfl_xor_sync(~0u, m, o));
        float s = 0.f;
        for (int l = lane; l < LP; l += 32) {
            float ev = expf(scores[l * NT + n] - m);
            scores[l * NT + n] = ev;
            s += ev;
        }
        #pragma unroll
        for (int o = 16; o; o >>= 1) s += __shfl_xor_sync(~0u, s, o);
        if (lane == 0) rowsum[n] = s;
    }
    __syncthreads();

    // ---- phase 3: attn_out[n][f] = sum_l attn * c -----------------------------
    if (t < FF) {
        float oc[NT];
        #pragma unroll
        for (int n = 0; n < NT; n++) oc[n] = 0.f;
        const float* cb = g_c + (size_t)b * LP * FF;
        for (int l = 0; l < LP; l++) {
            float cv = cb[(size_t)l * FF + t];
            const float4* sv = (const float4*)(scores + l * NT);
            #pragma unroll
            for (int q = 0; q < 4; q++) {
                float4 a = sv[q];
                oc[q*4+0] += a.x * cv; oc[q*4+1] += a.y * cv;
                oc[q*4+2] += a.z * cv; oc[q*4+3] += a.w * cv;
            }
        }
        #pragma unroll
        for (int n = 0; n < NT; n++) o_s[t * NT + n] = oc[n] / rowsum[n];
    }
    __syncthreads();

    // ---- phase 4: relu(attn_out @ Wo + bo) . graph_emb -> logits --------------
    float part[NT];
    #pragma unroll
    for (int n = 0; n < NT; n++) part[n] = 0.f;
    for (int feat = t; feat < FEAT; feat += 256) {
        float p[NT];
        float bov = bo[feat];
        #pragma unroll
        for (int n = 0; n < NT; n++) p[n] = bov;
        for (int f2 = 0; f2 < FF; f2++) {
            float wv = Wo[f2 * FEAT + feat];
            const float4* ov = (const float4*)(o_s + f2 * NT);
            #pragma unroll
            for (int q = 0; q < 4; q++) {
                float4 a = ov[q];
                p[q*4+0] += a.x * wv; p[q*4+1] += a.y * wv;
                p[q*4+2] += a.z * wv; p[q*4+3] += a.w * wv;
            }
        }
        #pragma unroll
        for (int n = 0; n < NT; n++) {
            int gn = n0 + n;
            if (gn < NLB) {
                float pv = fmaxf(p[n], 0.f);
                part[n] += pv * g_gemb[(size_t)gn * FEAT + feat];
            }
        }
    }
    #pragma unroll
    for (int n = 0; n < NT; n++) {
        float v = part[n];
        #pragma unroll
        for (int o = 16; o; o >>= 1) v += __shfl_xor_sync(~0u, v, o);
        if (lane == 0) wpart[n * 8 + w] = v;
    }
    __syncthreads();
    if (t < NT) {
        int gn = n0 + t;
        if (gn < NLB) {
            float s = 0.f;
            for (int i = 0; i < 8; i++) s += wpart[t * 8 + i];
            logits_out[b * NLB + gn] = s;
        }
    }
}

// ---------------- 6. BCE loss (deterministic two-stage) -----------------------
__global__ void k_loss_part(const float* __restrict__ y, const float* __restrict__ logits) {
    __shared__ float red[256];
    float s = 0.f;
    for (int i = blockIdx.x * 256 + threadIdx.x; i < BB * NLB; i += 64 * 256) {
        float z = logits[i];
        float yy = y[i];
        s += fmaxf(z, 0.f) - z * yy + log1pf(expf(-fabsf(z)));
    }
    red[threadIdx.x] = s;
    __syncthreads();
    for (int o = 128; o; o >>= 1) {
        if (threadIdx.x < o) red[threadIdx.x] += red[threadIdx.x + o];
        __syncthreads();
    }
    if (threadIdx.x == 0) g_losspart[blockIdx.x] = red[0];
}

__global__ void k_loss_final(float* __restrict__ out) {
    if (threadIdx.x == 0) {
        float s = 0.f;
        for (int i = 0; i < 64; i++) s += g_losspart[i];
        out[BB * NLB] = s / (float)BB;
    }
}

// ---------------- launch -------------------------------------------------------
extern "C" void kernel_launch(void* const* d_in, const int* in_sizes, int n_in,
                              void* d_out, int out_size) {
    const int*   x     = (const int*)d_in[0];
    const float* y     = (const float*)d_in[1];
    const float* mask  = (const float*)d_in[2];
    const float* we    = (const float*)d_in[3];
    const int*   lidx  = (const int*)d_in[4];
    const float* lmask = (const float*)d_in[5];
    const float* adj   = (const float*)d_in[6];
    const float* nn    = (const float*)d_in[7];
    const float* Wg    = (const float*)d_in[8];
    const float* bg    = (const float*)d_in[9];
    const float* Wc    = (const float*)d_in[10];
    const float* bc    = (const float*)d_in[11];
    const float* Wp    = (const float*)d_in[12];
    const float* bp    = (const float*)d_in[13];
    const float* Wo    = (const float*)d_in[14];
    const float* bo    = (const float*)d_in[15];
    float* out = (float*)d_out;

    const int conv_smem = (CT + KK - 1) * EE * (int)sizeof(float);   // 49200 B
    const int attn_smem = ATTN_SMEM_FLOATS * (int)sizeof(float);     // 160000 B
    cudaFuncSetAttribute(k_conv, cudaFuncAttributeMaxDynamicSharedMemorySize, conv_smem);
    cudaFuncSetAttribute(k_attn, cudaFuncAttributeMaxDynamicSharedMemorySize, attn_smem);

    k_avg<<<NLB, 320>>>(we, lidx, lmask);
    k_graph<<<NLB, 320>>>(adj, nn, Wg, bg);

    dim3 gc((LP + CT - 1) / CT, BB);
    k_conv<<<gc, 224, conv_smem>>>(x, mask, we, Wc, bc);
    k_pj<<<gc, 256>>>(Wp, bp);

    dim3 ga((NLB + NT - 1) / NT, BB);
    k_attn<<<ga, 256, attn_smem>>>(Wo, bo, out);

    k_loss_part<<<64, 256>>>(y, out);
    k_loss_final<<<1, 32>>>(out);
}

// round 6
// speedup vs baseline: 2.8782x; 2.8782x over previous
#include <cuda_runtime.h>
#include <math.h>

#define BB   8
#define LL   2000
#define EE   300
#define NLB  8922
#define LWW  10
#define FF   200
#define KK   10
#define HH   200
#define FEAT 500
#define LP   1991     // L - K + 1
#define LPAD 2048     // padded Lp for the scores buffer
#define CT   32       // conv l-tile

// ---------------- scratch (static device allocations; no cudaMalloc) ----------
__device__ float g_avg[NLB * EE];                       // 10.7 MB
__device__ float g_gemb[NLB * FEAT];                    // 17.8 MB
__device__ float g_c[(size_t)BB * LP * FF];             // 12.7 MB  [B][Lp][F]
__device__ float g_pjT[(size_t)BB * EE * LP];           // 19.1 MB  [B][E][Lp]
__device__ float g_scores[(size_t)BB * NLB * LPAD];     // 585 MB   [B][NL][LPAD]
__device__ float g_rowsum[BB * NLB];
__device__ float g_ao[(size_t)BB * NLB * FF];           // 57 MB
__device__ float g_losspart[64];

// ---------------- tf32 mma helpers --------------------------------------------
__device__ __forceinline__ unsigned cvt_tf32(float x) {
    unsigned u;
    asm("cvt.rna.tf32.f32 %0, %1;" : "=r"(u) : "f"(x));
    return u;
}

__device__ __forceinline__ void mma_tf32(float* d, const unsigned* a, const unsigned* b) {
    asm volatile(
        "mma.sync.aligned.m16n8k8.row.col.f32.tf32.tf32.f32 "
        "{%0,%1,%2,%3}, {%4,%5,%6,%7}, {%8,%9}, {%0,%1,%2,%3};"
        : "+f"(d[0]), "+f"(d[1]), "+f"(d[2]), "+f"(d[3])
        : "r"(a[0]), "r"(a[1]), "r"(a[2]), "r"(a[3]), "r"(b[0]), "r"(b[1]));
}

// ---------------- 1. average label embedding ----------------------------------
__global__ void k_avg(const float* __restrict__ we, const int* __restrict__ lidx,
                      const float* __restrict__ lmask) {
    int n = blockIdx.x;
    int t = threadIdx.x;
    __shared__ int   idx_s[LWW];
    __shared__ float m_s[LWW];
    __shared__ float inv;
    if (t < LWW) { idx_s[t] = lidx[n * LWW + t]; m_s[t] = lmask[n * LWW + t]; }
    __syncthreads();
    if (t == 0) {
        float s = 0.f;
        for (int w = 0; w < LWW; w++) s += m_s[w];
        inv = 1.f / s;
    }
    __syncthreads();
    if (t < EE) {
        float s = 0.f;
        for (int w = 0; w < LWW; w++)
            s += we[(size_t)idx_s[w] * EE + t] * m_s[w];
        g_avg[(size_t)n * EE + t] = s * inv;
    }
}

// ---------------- 2. sparse graph aggregate + Wg + concat ---------------------
__global__ void k_graph(const float* __restrict__ adj, const float* __restrict__ nn,
                        const float* __restrict__ Wg, const float* __restrict__ bg) {
    int n = blockIdx.x;
    int t = threadIdx.x;
    __shared__ int   list[256];
    __shared__ int   cnt;
    __shared__ float agg_s[EE];
    if (t == 0) cnt = 0;
    __syncthreads();
    for (int j = t; j < NLB; j += blockDim.x) {
        if (adj[(size_t)n * NLB + j] != 0.f) {
            int p = atomicAdd(&cnt, 1);
            if (p < 256) list[p] = j;
        }
    }
    __syncthreads();
    int m = cnt < 256 ? cnt : 256;
    if (t == 0) {            // deterministic ascending order
        for (int i = 1; i < m; i++) {
            int v = list[i], j = i - 1;
            while (j >= 0 && list[j] > v) { list[j + 1] = list[j]; j--; }
            list[j + 1] = v;
        }
    }
    __syncthreads();
    float invd = 1.f / nn[n];
    if (t < EE) {
        float s = 0.f;
        for (int i = 0; i < m; i++) s += g_avg[(size_t)list[i] * EE + t];
        agg_s[t] = s * invd;
        g_gemb[(size_t)n * FEAT + t] = g_avg[(size_t)n * EE + t];
    }
    __syncthreads();
    if (t < HH) {
        float s = bg[t];
        for (int e = 0; e < EE; e++) s += agg_s[e] * Wg[e * HH + t];
        g_gemb[(size_t)n * FEAT + EE + t] = fmaxf(s, 0.f);
    }
}

// ---------------- 3. document conv (im2col-free, reg-tiled) -------------------
__global__ void k_conv(const int* __restrict__ x, const float* __restrict__ mask,
                       const float* __restrict__ we, const float* __restrict__ Wc,
                       const float* __restrict__ bc) {
    extern __shared__ float xe_s[];            // (CT+KK-1)*EE = 41*300 floats
    const int TW = CT + KK - 1;                // 41
    int b  = blockIdx.y;
    int l0 = blockIdx.x * CT;
    int t  = threadIdx.x;                      // 224 threads

    for (int i = t; i < TW * EE; i += blockDim.x) {
        int tt = i / EE, e = i % EE;
        int gt = l0 + tt;
        float v = 0.f;
        if (gt < LL) v = we[(size_t)x[b * LL + gt] * EE + e] * mask[b * LL + gt];
        xe_s[i] = v;
    }
    __syncthreads();

    int f = t;
    if (f < FF) {
        float acc[CT];
        float bcv = bc[f];
        #pragma unroll
        for (int l = 0; l < CT; l++) acc[l] = bcv;
        const float* wrow = Wc + (size_t)f * EE * KK;
        for (int e = 0; e < EE; e++) {
            float wcr[KK];
            #pragma unroll
            for (int k = 0; k < KK; k++) wcr[k] = wrow[e * KK + k];
            #pragma unroll
            for (int tt = 0; tt < TW; tt++) {
                float xv = xe_s[tt * EE + e];
                #pragma unroll
                for (int k = 0; k < KK; k++) {
                    int l = tt - k;
                    if (l >= 0 && l < CT) acc[l] += xv * wcr[k];
                }
            }
        }
        #pragma unroll
        for (int l = 0; l < CT; l++) {
            int gl = l0 + l;
            if (gl < LP)
                g_c[((size_t)b * LP + gl) * FF + f] = fmaxf(acc[l], 0.f);
        }
    }
}

// ---------------- 4. pj = tanh(c @ Wp + bp), stored transposed [B][E][Lp] ----
__global__ void k_pj(const float* __restrict__ Wp, const float* __restrict__ bp) {
    __shared__ float c_s[CT * 201];            // pad 201 -> conflict-free
    int b  = blockIdx.y;
    int l0 = blockIdx.x * CT;
    int t  = threadIdx.x;                      // 256
    for (int i = t; i < CT * FF; i += 256) {
        int l = i / FF, f = i % FF;
        int gl = l0 + l;
        c_s[l * 201 + f] = (gl < LP) ? g_c[((size_t)b * LP + gl) * FF + f] : 0.f;
    }
    __syncthreads();
    int l  = t & 31;
    int eg = t >> 5;                           // 8 e-groups
    int gl = l0 + l;
    for (int e = eg; e < EE; e += 8) {
        float s = bp[e];
        for (int f = 0; f < FF; f++) s += c_s[l * 201 + f] * Wp[f * EE + e];
        if (gl < LP)
            g_pjT[((size_t)b * EE + e) * LP + gl] = tanhf(s);
    }
}

// ---------------- 5a. scores GEMM (tf32 mma): scores = avg @ pjT --------------
// block tile 128(M labels) x 128(N l-positions), K chunk 16, double-buffered.
// warp layout: 8 warps = 4(m) x 2(n); warp tile 32x64.
__global__ void __launch_bounds__(256) k_scores() {
    __shared__ __align__(16) unsigned sA[2][2][8][32][4];   // [buf][k8][tm16][lane][4]
    __shared__ __align__(16) unsigned sB[2][2][16][32][2];  // [buf][k8][tn8][lane][2]

    int b  = blockIdx.z;
    int m0 = blockIdx.x * 128;
    int n0 = blockIdx.y * 128;
    const float* Ap = g_avg;
    const float* Bp = g_pjT + (size_t)b * EE * LP;

    int t = threadIdx.x, lane = t & 31, wid = t >> 5;
    int wm = wid >> 1, wn = wid & 1;

    float acc[2][8][4];
    #pragma unroll
    for (int i = 0; i < 2; i++)
        #pragma unroll
        for (int j = 0; j < 8; j++)
            #pragma unroll
            for (int q = 0; q < 4; q++) acc[i][j][q] = 0.f;

    float ra[2][4];
    float rb[4][2];

    auto loadA = [&](int k0) {
        #pragma unroll
        for (int s = 0; s < 2; s++) {
            int slot = t + s * 256;
            int ls = slot & 31, tm = (slot >> 5) & 7, k8 = slot >> 8;
            int r = m0 + tm * 16 + (ls >> 2);
            int c = k0 + k8 * 8 + (ls & 3);
            bool rv0 = r < NLB, rv1 = (r + 8) < NLB;
            bool cv0 = c < EE,  cv1 = (c + 4) < EE;
            ra[s][0] = (rv0 && cv0) ? Ap[(size_t)r * EE + c]           : 0.f;
            ra[s][1] = (rv1 && cv0) ? Ap[(size_t)(r + 8) * EE + c]     : 0.f;
            ra[s][2] = (rv0 && cv1) ? Ap[(size_t)r * EE + c + 4]       : 0.f;
            ra[s][3] = (rv1 && cv1) ? Ap[(size_t)(r + 8) * EE + c + 4] : 0.f;
        }
    };
    auto loadB = [&](int k0) {
        #pragma unroll
        for (int s = 0; s < 4; s++) {
            int slot = t + s * 256;
            int ls = slot & 31, tn = (slot >> 5) & 15, k8 = slot >> 9;
            int k = k0 + k8 * 8 + (ls & 3);
            int l = n0 + tn * 8 + (ls >> 2);
            bool lv = l < LP;
            rb[s][0] = (k < EE && lv)       ? Bp[(size_t)k * LP + l]       : 0.f;
            rb[s][1] = ((k + 4) < EE && lv) ? Bp[(size_t)(k + 4) * LP + l] : 0.f;
        }
    };
    auto storeS = [&](int buf) {
        #pragma unroll
        for (int s = 0; s < 2; s++) {
            int slot = t + s * 256;
            int ls = slot & 31, tm = (slot >> 5) & 7, k8 = slot >> 8;
            unsigned* d = &sA[buf][k8][tm][ls][0];
            d[0] = cvt_tf32(ra[s][0]); d[1] = cvt_tf32(ra[s][1]);
            d[2] = cvt_tf32(ra[s][2]); d[3] = cvt_tf32(ra[s][3]);
        }
        #pragma unroll
        for (int s = 0; s < 4; s++) {
            int slot = t + s * 256;
            int ls = slot & 31, tn = (slot >> 5) & 15, k8 = slot >> 9;
            unsigned* d = &sB[buf][k8][tn][ls][0];
            d[0] = cvt_tf32(rb[s][0]); d[1] = cvt_tf32(rb[s][1]);
        }
    };
    auto compute = [&](int buf) {
        #pragma unroll
        for (int k8 = 0; k8 < 2; k8++) {
            unsigned af[2][4], bf[8][2];
            #pragma unroll
            for (int i = 0; i < 2; i++)
                *(uint4*)af[i] = *(const uint4*)&sA[buf][k8][wm * 2 + i][lane][0];
            #pragma unroll
            for (int j = 0; j < 8; j++)
                *(uint2*)bf[j] = *(const uint2*)&sB[buf][k8][wn * 8 + j][lane][0];
            #pragma unroll
            for (int i = 0; i < 2; i++)
                #pragma unroll
                for (int j = 0; j < 8; j++)
                    mma_tf32(acc[i][j], af[i], bf[j]);
        }
    };

    const int S = (EE + 15) / 16;   // 19 stages
    loadA(0); loadB(0); storeS(0);
    __syncthreads();
    for (int s = 0; s < S; s++) {
        if (s + 1 < S) { loadA((s + 1) * 16); loadB((s + 1) * 16); }
        compute(s & 1);
        if (s + 1 < S) storeS((s + 1) & 1);
        __syncthreads();
    }

    // epilogue: raw scores (pad cols get exact 0 from zero-padded B)
    #pragma unroll
    for (int i = 0; i < 2; i++) {
        int row = m0 + (wm * 2 + i) * 16 + (lane >> 2);
        #pragma unroll
        for (int j = 0; j < 8; j++) {
            int col = n0 + (wn * 8 + j) * 8 + (lane & 3) * 2;
            size_t base = ((size_t)(b * NLB + row)) * LPAD + col;
            if (row < NLB) {
                float2 o0 = make_float2(acc[i][j][0], acc[i][j][1]);
                *(float2*)&g_scores[base] = o0;
            }
            if (row + 8 < NLB) {
                float2 o1 = make_float2(acc[i][j][2], acc[i][j][3]);
                *(float2*)&g_scores[base + (size_t)8 * LPAD] = o1;
            }
        }
    }
}

// ---------------- 5b. row softmax (exp + rowsum, in-place) --------------------
__global__ void __launch_bounds__(256) k_softmax() {
    int wid = threadIdx.x >> 5, lane = threadIdx.x & 31;
    int row = blockIdx.x * 8 + wid;            // row < BB*NLB
    float4* p = (float4*)(g_scores + (size_t)row * LPAD);
    float4 v[16];
    float m = -1e30f;
    #pragma unroll
    for (int q = 0; q < 16; q++) {
        v[q] = p[q * 32 + lane];
        int base = (q * 32 + lane) * 4;
        if (base + 0 < LP) m = fmaxf(m, v[q].x);
        if (base + 1 < LP) m = fmaxf(m, v[q].y);
        if (base + 2 < LP) m = fmaxf(m, v[q].z);
        if (base + 3 < LP) m = fmaxf(m, v[q].w);
    }
    #pragma unroll
    for (int o = 16; o; o >>= 1) m = fmaxf(m, __shfl_xor_sync(~0u, m, o));
    float s = 0.f;
    #pragma unroll
    for (int q = 0; q < 16; q++) {
        int base = (q * 32 + lane) * 4;
        v[q].x = (base + 0 < LP) ? expf(v[q].x - m) : 0.f;
        v[q].y = (base + 1 < LP) ? expf(v[q].y - m) : 0.f;
        v[q].z = (base + 2 < LP) ? expf(v[q].z - m) : 0.f;
        v[q].w = (base + 3 < LP) ? expf(v[q].w - m) : 0.f;
        s += v[q].x + v[q].y + v[q].z + v[q].w;
        p[q * 32 + lane] = v[q];
    }
    #pragma unroll
    for (int o = 16; o; o >>= 1) s += __shfl_xor_sync(~0u, s, o);
    if (lane == 0) g_rowsum[row] = s;
}

// ---------------- 5c. attn_out GEMM (tf32 mma): exp_scores @ c, /rowsum -------
__global__ void __launch_bounds__(256) k_attnout() {
    __shared__ __align__(16) unsigned sA[2][2][8][32][4];
    __shared__ __align__(16) unsigned sB[2][2][16][32][2];

    int b  = blockIdx.z;
    int m0 = blockIdx.x * 128;
    int n0 = blockIdx.y * 128;
    const float* Ap = g_scores + (size_t)b * NLB * LPAD;
    const float* Bp = g_c + (size_t)b * LP * FF;

    int t = threadIdx.x, lane = t & 31, wid = t >> 5;
    int wm = wid >> 1, wn = wid & 1;

    float acc[2][8][4];
    #pragma unroll
    for (int i = 0; i < 2; i++)
        #pragma unroll
        for (int j = 0; j < 8; j++)
            #pragma unroll
            for (int q = 0; q < 4; q++) acc[i][j][q] = 0.f;

    float ra[2][4];
    float rb[4][2];

    auto loadA = [&](int k0) {
        #pragma unroll
        for (int s = 0; s < 2; s++) {
            int slot = t + s * 256;
            int ls = slot & 31, tm = (slot >> 5) & 7, k8 = slot >> 8;
            int r = m0 + tm * 16 + (ls >> 2);
            int c = k0 + k8 * 8 + (ls & 3);
            bool rv0 = r < NLB, rv1 = (r + 8) < NLB;
            ra[s][0] = rv0 ? Ap[(size_t)r * LPAD + c]           : 0.f;
            ra[s][1] = rv1 ? Ap[(size_t)(r + 8) * LPAD + c]     : 0.f;
            ra[s][2] = rv0 ? Ap[(size_t)r * LPAD + c + 4]       : 0.f;
            ra[s][3] = rv1 ? Ap[(size_t)(r + 8) * LPAD + c + 4] : 0.f;
        }
    };
    auto loadB = [&](int k0) {
        #pragma unroll
        for (int s = 0; s < 4; s++) {
            int slot = t + s * 256;
            int ls = slot & 31, tn = (slot >> 5) & 15, k8 = slot >> 9;
            int k = k0 + k8 * 8 + (ls & 3);
            int n = n0 + tn * 8 + (ls >> 2);
            bool nv = n < FF;
            rb[s][0] = (k < LP && nv)       ? Bp[(size_t)k * FF + n]       : 0.f;
            rb[s][1] = ((k + 4) < LP && nv) ? Bp[(size_t)(k + 4) * FF + n] : 0.f;
        }
    };
    auto storeS = [&](int buf) {
        #pragma unroll
        for (int s = 0; s < 2; s++) {
            int slot = t + s * 256;
            int ls = slot & 31, tm = (slot >> 5) & 7, k8 = slot >> 8;
            unsigned* d = &sA[buf][k8][tm][ls][0];
            d[0] = cvt_tf32(ra[s][0]); d[1] = cvt_tf32(ra[s][1]);
            d[2] = cvt_tf32(ra[s][2]); d[3] = cvt_tf32(ra[s][3]);
        }
        #pragma unroll
        for (int s = 0; s < 4; s++) {
            int slot = t + s * 256;
            int ls = slot & 31, tn = (slot >> 5) & 15, k8 = slot >> 9;
            unsigned* d = &sB[buf][k8][tn][ls][0];
            d[0] = cvt_tf32(rb[s][0]); d[1] = cvt_tf32(rb[s][1]);
        }
    };
    auto compute = [&](int buf) {
        #pragma unroll
        for (int k8 = 0; k8 < 2; k8++) {
            unsigned af[2][4], bf[8][2];
            #pragma unroll
            for (int i = 0; i < 2; i++)
                *(uint4*)af[i] = *(const uint4*)&sA[buf][k8][wm * 2 + i][lane][0];
            #pragma unroll
            for (int j = 0; j < 8; j++)
                *(uint2*)bf[j] = *(const uint2*)&sB[buf][k8][wn * 8 + j][lane][0];
            #pragma unroll
            for (int i = 0; i < 2; i++)
                #pragma unroll
                for (int j = 0; j < 8; j++)
                    mma_tf32(acc[i][j], af[i], bf[j]);
        }
    };

    const int S = LPAD / 16;   // 128 stages
    loadA(0); loadB(0); storeS(0);
    __syncthreads();
    for (int s = 0; s < S; s++) {
        if (s + 1 < S) { loadA((s + 1) * 16); loadB((s + 1) * 16); }
        compute(s & 1);
        if (s + 1 < S) storeS((s + 1) & 1);
        __syncthreads();
    }

    int bNL = b * NLB;
    #pragma unroll
    for (int i = 0; i < 2; i++) {
        int row = m0 + (wm * 2 + i) * 16 + (lane >> 2);
        float inv0 = (row < NLB)     ? 1.f / g_rowsum[bNL + row]     : 0.f;
        float inv1 = (row + 8 < NLB) ? 1.f / g_rowsum[bNL + row + 8] : 0.f;
        #pragma unroll
        for (int j = 0; j < 8; j++) {
            int col = n0 + (wn * 8 + j) * 8 + (lane & 3) * 2;
            if (col < FF) {
                if (row < NLB) {
                    float2 o = make_float2(acc[i][j][0] * inv0, acc[i][j][1] * inv0);
                    *(float2*)&g_ao[((size_t)(bNL + row)) * FF + col] = o;
                }
                if (row + 8 < NLB) {
                    float2 o = make_float2(acc[i][j][2] * inv1, acc[i][j][3] * inv1);
                    *(float2*)&g_ao[((size_t)(bNL + row + 8)) * FF + col] = o;
                }
            }
        }
    }
}

// ---------------- 5d. proj = relu(ao @ Wo + bo) . gemb -> logits --------------
__global__ void __launch_bounds__(256) k_proj(const float* __restrict__ Wo,
                                              const float* __restrict__ bo,
                                              float* __restrict__ out) {
    __shared__ float ao_s[FF * 36];            // [f][n] padded stride 36
    __shared__ float wred[32 * 8];
    int b  = blockIdx.y;
    int n0 = blockIdx.x * 32;
    int t  = threadIdx.x, lane = t & 31, wid = t >> 5;

    for (int i = t; i < 32 * FF; i += 256) {
        int n = i / FF, f = i % FF;
        float v = (n0 + n < NLB) ? g_ao[((size_t)(b * NLB + n0 + n)) * FF + f] : 0.f;
        ao_s[f * 36 + n] = v;
    }
    __syncthreads();

    int f0 = 2 * t, f1 = 2 * t + 1;
    bool v0 = f0 < FEAT, v1 = f1 < FEAT;
    float p0[32], p1[32];
    float b0v = v0 ? bo[f0] : 0.f;
    float b1v = v1 ? bo[f1] : 0.f;
    #pragma unroll
    for (int n = 0; n < 32; n++) { p0[n] = b0v; p1[n] = b1v; }

    for (int f2 = 0; f2 < FF; f2++) {
        float w0 = v0 ? Wo[f2 * FEAT + f0] : 0.f;
        float w1 = v1 ? Wo[f2 * FEAT + f1] : 0.f;
        const float4* a4 = (const float4*)(ao_s + f2 * 36);
        #pragma unroll
        for (int q = 0; q < 8; q++) {
            float4 a = a4[q];
            p0[q * 4 + 0] += a.x * w0; p0[q * 4 + 1] += a.y * w0;
            p0[q * 4 + 2] += a.z * w0; p0[q * 4 + 3] += a.w * w0;
            p1[q * 4 + 0] += a.x * w1; p1[q * 4 + 1] += a.y * w1;
            p1[q * 4 + 2] += a.z * w1; p1[q * 4 + 3] += a.w * w1;
        }
    }

    float part[32];
    #pragma unroll
    for (int n = 0; n < 32; n++) {
        int gn = n0 + n;
        float g0 = (v0 && gn < NLB) ? g_gemb[(size_t)gn * FEAT + f0] : 0.f;
        float g1 = (v1 && gn < NLB) ? g_gemb[(size_t)gn * FEAT + f1] : 0.f;
        part[n] = fmaxf(p0[n], 0.f) * g0 + fmaxf(p1[n], 0.f) * g1;
    }
    #pragma unroll
    for (int n = 0; n < 32; n++) {
        float v = part[n];
        #pragma unroll
        for (int o = 16; o; o >>= 1) v += __shfl_xor_sync(~0u, v, o);
        if (lane == 0) wred[n * 8 + wid] = v;
    }
    __syncthreads();
    if (t < 32) {
        int gn = n0 + t;
        if (gn < NLB) {
            float s = 0.f;
            #pragma unroll
            for (int i = 0; i < 8; i++) s += wred[t * 8 + i];
            out[b * NLB + gn] = s;
        }
    }
}

// ---------------- 6. BCE loss (deterministic two-stage) -----------------------
__global__ void k_loss_part(const float* __restrict__ y, const float* __restrict__ logits) {
    __shared__ float red[256];
    float s = 0.f;
    for (int i = blockIdx.x * 256 + threadIdx.x; i < BB * NLB; i += 64 * 256) {
        float z = logits[i];
        float yy = y[i];
        s += fmaxf(z, 0.f) - z * yy + log1pf(expf(-fabsf(z)));
    }
    red[threadIdx.x] = s;
    __syncthreads();
    for (int o = 128; o; o >>= 1) {
        if (threadIdx.x < o) red[threadIdx.x] += red[threadIdx.x + o];
        __syncthreads();
    }
    if (threadIdx.x == 0) g_losspart[blockIdx.x] = red[0];
}

__global__ void k_loss_final(float* __restrict__ out) {
    if (threadIdx.x == 0) {
        float s = 0.f;
        for (int i = 0; i < 64; i++) s += g_losspart[i];
        out[BB * NLB] = s / (float)BB;
    }
}

// ---------------- launch -------------------------------------------------------
extern "C" void kernel_launch(void* const* d_in, const int* in_sizes, int n_in,
                              void* d_out, int out_size) {
    const int*   x     = (const int*)d_in[0];
    const float* y     = (const float*)d_in[1];
    const float* mask  = (const float*)d_in[2];
    const float* we    = (const float*)d_in[3];
    const int*   lidx  = (const int*)d_in[4];
    const float* lmask = (const float*)d_in[5];
    const float* adj   = (const float*)d_in[6];
    const float* nn    = (const float*)d_in[7];
    const float* Wg    = (const float*)d_in[8];
    const float* bg    = (const float*)d_in[9];
    const float* Wc    = (const float*)d_in[10];
    const float* bc    = (const float*)d_in[11];
    const float* Wp    = (const float*)d_in[12];
    const float* bp    = (const float*)d_in[13];
    const float* Wo    = (const float*)d_in[14];
    const float* bo    = (const float*)d_in[15];
    float* out = (float*)d_out;

    const int conv_smem = (CT + KK - 1) * EE * (int)sizeof(float);   // 49200 B
    cudaFuncSetAttribute(k_conv, cudaFuncAttributeMaxDynamicSharedMemorySize, conv_smem);

    k_avg<<<NLB, 320>>>(we, lidx, lmask);
    k_graph<<<NLB, 320>>>(adj, nn, Wg, bg);

    dim3 gc((LP + CT - 1) / CT, BB);
    k_conv<<<gc, 224, conv_smem>>>(x, mask, we, Wc, bc);
    k_pj<<<gc, 256>>>(Wp, bp);

    dim3 gs((NLB + 127) / 128, LPAD / 128, BB);      // 70 x 16 x 8
    k_scores<<<gs, 256>>>();

    k_softmax<<<(BB * NLB) / 8, 256>>>();

    dim3 go((NLB + 127) / 128, (FF + 127) / 128, BB); // 70 x 2 x 8
    k_attnout<<<go, 256>>>();

    dim3 gp((NLB + 31) / 32, BB);
    k_proj<<<gp, 256>>>(Wo, bo, out);

    k_loss_part<<<64, 256>>>(y, out);
    k_loss_final<<<1, 32>>>(out);
}

// round 8
// speedup vs baseline: 4.4200x; 1.5357x over previous
#include <cuda_runtime.h>
#include <math.h>

#define BB   8
#define LL   2000
#define EE   300
#define NLB  8922
#define LWW  10
#define FF   200
#define KK   10
#define HH   200
#define FEAT 500
#define LP   1991     // L - K + 1
#define LPAD 2048     // padded Lp for the scores buffer
#define CKK  3000     // conv GEMM K = E*K

// ---------------- scratch (static device allocations; no cudaMalloc) ----------
__device__ float g_avg[NLB * EE];                       // 10.7 MB
__device__ float g_gemb[NLB * FEAT];                    // 17.8 MB
__device__ float g_c[(size_t)BB * LP * FF];             // 12.7 MB  [B][Lp][F]
__device__ float g_pjT[(size_t)BB * EE * LP];           // 19.1 MB  [B][E][Lp]
__device__ float g_scores[(size_t)BB * NLB * LPAD];     // 585 MB   [B][NL][LPAD]
__device__ float g_rowsum[BB * NLB];
__device__ float g_ao[(size_t)BB * NLB * FF];           // 57 MB
__device__ float g_xeT[(size_t)BB * EE * LL];           // 19.2 MB  [B][E][L]
__device__ float g_wcT[CKK * FF];                       // 2.4 MB   [(e,k)][F]
__device__ float g_losspart[64];

// ---------------- tf32 mma helpers --------------------------------------------
__device__ __forceinline__ unsigned cvt_tf32(float x) {
    unsigned u;
    asm("cvt.rna.tf32.f32 %0, %1;" : "=r"(u) : "f"(x));
    return u;
}

__device__ __forceinline__ void mma_tf32(float* d, const unsigned* a, const unsigned* b) {
    asm volatile(
        "mma.sync.aligned.m16n8k8.row.col.f32.tf32.tf32.f32 "
        "{%0,%1,%2,%3}, {%4,%5,%6,%7}, {%8,%9}, {%0,%1,%2,%3};"
        : "+f"(d[0]), "+f"(d[1]), "+f"(d[2]), "+f"(d[3])
        : "r"(a[0]), "r"(a[1]), "r"(a[2]), "r"(a[3]), "r"(b[0]), "r"(b[1]));
}

// ---------------- 1. average label embedding ----------------------------------
__global__ void k_avg(const float* __restrict__ we, const int* __restrict__ lidx,
                      const float* __restrict__ lmask) {
    int n = blockIdx.x;
    int t = threadIdx.x;
    __shared__ int   idx_s[LWW];
    __shared__ float m_s[LWW];
    __shared__ float inv;
    if (t < LWW) { idx_s[t] = lidx[n * LWW + t]; m_s[t] = lmask[n * LWW + t]; }
    __syncthreads();
    if (t == 0) {
        float s = 0.f;
        for (int w = 0; w < LWW; w++) s += m_s[w];
        inv = 1.f / s;
    }
    __syncthreads();
    if (t < EE) {
        float s = 0.f;
        for (int w = 0; w < LWW; w++)
            s += we[(size_t)idx_s[w] * EE + t] * m_s[w];
        g_avg[(size_t)n * EE + t] = s * inv;
    }
}

// ---------------- 2. sparse graph aggregate + Wg + concat ---------------------
__global__ void k_graph(const float* __restrict__ adj, const float* __restrict__ nn,
                        const float* __restrict__ Wg, const float* __restrict__ bg) {
    int n = blockIdx.x;
    int t = threadIdx.x;
    __shared__ int   list[256];
    __shared__ int   cnt;
    __shared__ float agg_s[EE];
    if (t == 0) cnt = 0;
    __syncthreads();
    for (int j = t; j < NLB; j += blockDim.x) {
        if (adj[(size_t)n * NLB + j] != 0.f) {
            int p = atomicAdd(&cnt, 1);
            if (p < 256) list[p] = j;
        }
    }
    __syncthreads();
    int m = cnt < 256 ? cnt : 256;
    if (t == 0) {            // deterministic ascending order
        for (int i = 1; i < m; i++) {
            int v = list[i], j = i - 1;
            while (j >= 0 && list[j] > v) { list[j + 1] = list[j]; j--; }
            list[j + 1] = v;
        }
    }
    __syncthreads();
    float invd = 1.f / nn[n];
    if (t < EE) {
        float s = 0.f;
        for (int i = 0; i < m; i++) s += g_avg[(size_t)list[i] * EE + t];
        agg_s[t] = s * invd;
        g_gemb[(size_t)n * FEAT + t] = g_avg[(size_t)n * EE + t];
    }
    __syncthreads();
    if (t < HH) {
        float s = bg[t];
        for (int e = 0; e < EE; e++) s += agg_s[e] * Wg[e * HH + t];
        g_gemb[(size_t)n * FEAT + EE + t] = fmaxf(s, 0.f);
    }
}

// ---------------- 3a. xeT[b][e][l] = we[x[b][l]][e] * mask[b][l] --------------
__global__ void k_embT(const int* __restrict__ x, const float* __restrict__ mask,
                       const float* __restrict__ we) {
    __shared__ int   xi[128];
    __shared__ float mk[128];
    int b  = blockIdx.y;
    int l0 = blockIdx.x * 128;
    int t  = threadIdx.x;
    if (t < 128) {
        int gl = l0 + t;
        xi[t] = (gl < LL) ? x[b * LL + gl] : 0;
        mk[t] = (gl < LL) ? mask[b * LL + gl] : 0.f;
    }
    __syncthreads();
    int l = t & 127, e0 = t >> 7;
    int gl = l0 + l;
    if (gl < LL) {
        const float* wr = we + (size_t)xi[l] * EE;
        float m = mk[l];
        for (int e = e0; e < EE; e += 2)
            g_xeT[((size_t)b * EE + e) * LL + gl] = wr[e] * m;
    }
}

// ---------------- 3b. WcT[(e*K+k)][f] = Wc[f][e][k] ---------------------------
__global__ void k_wct(const float* __restrict__ Wc) {
    int idx = blockIdx.x * 256 + threadIdx.x;
    if (idx < CKK * FF) {
        int c = idx / FF, f = idx % FF;
        g_wcT[idx] = Wc[(size_t)f * CKK + c];
    }
}

// ---------------- 3c. conv GEMM (tf32): c = relu(im2col(xeT) @ WcT + bc) ------
__global__ void __launch_bounds__(256) k_convg(const float* __restrict__ bc) {
    __shared__ __align__(16) unsigned sA[2][2][8][32][4];
    __shared__ __align__(16) unsigned sB[2][2][16][32][2];

    int b  = blockIdx.z;
    int m0 = blockIdx.x * 128;      // l
    int n0 = blockIdx.y * 128;      // f
    const float* Ap = g_xeT + (size_t)b * EE * LL;

    int t = threadIdx.x, lane = t & 31, wid = t >> 5;
    int wm = wid >> 1, wn = wid & 1;

    float acc[2][8][4];
    #pragma unroll
    for (int i = 0; i < 2; i++)
        #pragma unroll
        for (int j = 0; j < 8; j++)
            #pragma unroll
            for (int q = 0; q < 4; q++) acc[i][j][q] = 0.f;

    float ra[2][4];
    float rb[4][2];

    auto loadA = [&](int k0) {
        #pragma unroll
        for (int s = 0; s < 2; s++) {
            int slot = t + s * 256;
            int ls = slot & 31, tm = (slot >> 5) & 7, k8 = slot >> 8;
            int r  = m0 + tm * 16 + (ls >> 2);
            int c  = k0 + k8 * 8 + (ls & 3);
            int c2 = c + 4;
            int e1 = c / KK,  o1 = c  - e1 * KK;
            int e2 = c2 / KK, o2 = c2 - e2 * KK;
            bool rv0 = r < LP, rv1 = (r + 8) < LP;
            bool cv1 = c < CKK, cv2 = c2 < CKK;
            ra[s][0] = (rv0 && cv1) ? Ap[(size_t)e1 * LL + r + o1]     : 0.f;
            ra[s][1] = (rv1 && cv1) ? Ap[(size_t)e1 * LL + r + 8 + o1] : 0.f;
            ra[s][2] = (rv0 && cv2) ? Ap[(size_t)e2 * LL + r + o2]     : 0.f;
            ra[s][3] = (rv1 && cv2) ? Ap[(size_t)e2 * LL + r + 8 + o2] : 0.f;
        }
    };
    auto loadB = [&](int k0) {
        #pragma unroll
        for (int s = 0; s < 4; s++) {
            int slot = t + s * 256;
            int ls = slot & 31, tn = (slot >> 5) & 15, k8 = slot >> 9;
            int k = k0 + k8 * 8 + (ls & 3);
            int n = n0 + tn * 8 + (ls >> 2);
            bool nv = n < FF;
            rb[s][0] = (k < CKK && nv)       ? g_wcT[(size_t)k * FF + n]       : 0.f;
            rb[s][1] = ((k + 4) < CKK && nv) ? g_wcT[(size_t)(k + 4) * FF + n] : 0.f;
        }
    };
    auto storeS = [&](int buf) {
        #pragma unroll
        for (int s = 0; s < 2; s++) {
            int slot = t + s * 256;
            int ls = slot & 31, tm = (slot >> 5) & 7, k8 = slot >> 8;
            unsigned* d = &sA[buf][k8][tm][ls][0];
            d[0] = cvt_tf32(ra[s][0]); d[1] = cvt_tf32(ra[s][1]);
            d[2] = cvt_tf32(ra[s][2]); d[3] = cvt_tf32(ra[s][3]);
        }
        #pragma unroll
        for (int s = 0; s < 4; s++) {
            int slot = t + s * 256;
            int ls = slot & 31, tn = (slot >> 5) & 15, k8 = slot >> 9;
            unsigned* d = &sB[buf][k8][tn][ls][0];
            d[0] = cvt_tf32(rb[s][0]); d[1] = cvt_tf32(rb[s][1]);
        }
    };
    auto compute = [&](int buf) {
        #pragma unroll
        for (int k8 = 0; k8 < 2; k8++) {
            unsigned af[2][4], bf[8][2];
            #pragma unroll
            for (int i = 0; i < 2; i++)
                *(uint4*)af[i] = *(const uint4*)&sA[buf][k8][wm * 2 + i][lane][0];
            #pragma unroll
            for (int j = 0; j < 8; j++)
                *(uint2*)bf[j] = *(const uint2*)&sB[buf][k8][wn * 8 + j][lane][0];
            #pragma unroll
            for (int i = 0; i < 2; i++)
                #pragma unroll
                for (int j = 0; j < 8; j++)
                    mma_tf32(acc[i][j], af[i], bf[j]);
        }
    };

    const int S = (CKK + 15) / 16;   // 188
    loadA(0); loadB(0); storeS(0);
    __syncthreads();
    for (int s = 0; s < S; s++) {
        if (s + 1 < S) { loadA((s + 1) * 16); loadB((s + 1) * 16); }
        compute(s & 1);
        if (s + 1 < S) storeS((s + 1) & 1);
        __syncthreads();
    }

    #pragma unroll
    for (int i = 0; i < 2; i++) {
        int row = m0 + (wm * 2 + i) * 16 + (lane >> 2);
        #pragma unroll
        for (int j = 0; j < 8; j++) {
            int col = n0 + (wn * 8 + j) * 8 + (lane & 3) * 2;
            if (col < FF) {
                float b0 = bc[col], b1 = bc[col + 1];
                if (row < LP) {
                    float2 o = make_float2(fmaxf(acc[i][j][0] + b0, 0.f),
                                           fmaxf(acc[i][j][1] + b1, 0.f));
                    *(float2*)&g_c[((size_t)b * LP + row) * FF + col] = o;
                }
                if (row + 8 < LP) {
                    float2 o = make_float2(fmaxf(acc[i][j][2] + b0, 0.f),
                                           fmaxf(acc[i][j][3] + b1, 0.f));
                    *(float2*)&g_c[((size_t)b * LP + row + 8) * FF + col] = o;
                }
            }
        }
    }
}

// ---------------- 4. pj GEMM (tf32): pjT = tanh(c @ Wp + bp)^T ----------------
__global__ void __launch_bounds__(256) k_pjg(const float* __restrict__ Wp,
                                             const float* __restrict__ bp) {
    __shared__ __align__(16) unsigned sA[2][2][8][32][4];
    __shared__ __align__(16) unsigned sB[2][2][16][32][2];

    int b  = blockIdx.z;
    int m0 = blockIdx.x * 128;      // l
    int n0 = blockIdx.y * 128;      // e
    const float* Ap = g_c + (size_t)b * LP * FF;

    int t = threadIdx.x, lane = t & 31, wid = t >> 5;
    int wm = wid >> 1, wn = wid & 1;

    float acc[2][8][4];
    #pragma unroll
    for (int i = 0; i < 2; i++)
        #pragma unroll
        for (int j = 0; j < 8; j++)
            #pragma unroll
            for (int q = 0; q < 4; q++) acc[i][j][q] = 0.f;

    float ra[2][4];
    float rb[4][2];

    auto loadA = [&](int k0) {
        #pragma unroll
        for (int s = 0; s < 2; s++) {
            int slot = t + s * 256;
            int ls = slot & 31, tm = (slot >> 5) & 7, k8 = slot >> 8;
            int r = m0 + tm * 16 + (ls >> 2);
            int c = k0 + k8 * 8 + (ls & 3);
            bool rv0 = r < LP, rv1 = (r + 8) < LP;
            bool cv0 = c < FF, cv1 = (c + 4) < FF;
            ra[s][0] = (rv0 && cv0) ? Ap[(size_t)r * FF + c]           : 0.f;
            ra[s][1] = (rv1 && cv0) ? Ap[(size_t)(r + 8) * FF + c]     : 0.f;
            ra[s][2] = (rv0 && cv1) ? Ap[(size_t)r * FF + c + 4]       : 0.f;
            ra[s][3] = (rv1 && cv1) ? Ap[(size_t)(r + 8) * FF + c + 4] : 0.f;
        }
    };
    auto loadB = [&](int k0) {
        #pragma unroll
        for (int s = 0; s < 4; s++) {
            int slot = t + s * 256;
            int ls = slot & 31, tn = (slot >> 5) & 15, k8 = slot >> 9;
            int k = k0 + k8 * 8 + (ls & 3);
            int n = n0 + tn * 8 + (ls >> 2);
            bool nv = n < EE;
            rb[s][0] = (k < FF && nv)       ? Wp[(size_t)k * EE + n]       : 0.f;
            rb[s][1] = ((k + 4) < FF && nv) ? Wp[(size_t)(k + 4) * EE + n] : 0.f;
        }
    };
    auto storeS = [&](int buf) {
        #pragma unroll
        for (int s = 0; s < 2; s++) {
            int slot = t + s * 256;
            int ls = slot & 31, tm = (slot >> 5) & 7, k8 = slot >> 8;
            unsigned* d = &sA[buf][k8][tm][ls][0];
            d[0] = cvt_tf32(ra[s][0]); d[1] = cvt_tf32(ra[s][1]);
            d[2] = cvt_tf32(ra[s][2]); d[3] = cvt_tf32(ra[s][3]);
        }
        #pragma unroll
        for (int s = 0; s < 4; s++) {
            int slot = t + s * 256;
            int ls = slot & 31, tn = (slot >> 5) & 15, k8 = slot >> 9;
            unsigned* d = &sB[buf][k8][tn][ls][0];
            d[0] = cvt_tf32(rb[s][0]); d[1] = cvt_tf32(rb[s][1]);
        }
    };
    auto compute = [&](int buf) {
        #pragma unroll
        for (int k8 = 0; k8 < 2; k8++) {
            unsigned af[2][4], bf[8][2];
            #pragma unroll
            for (int i = 0; i < 2; i++)
                *(uint4*)af[i] = *(const uint4*)&sA[buf][k8][wm * 2 + i][lane][0];
            #pragma unroll
            for (int j = 0; j < 8; j++)
                *(uint2*)bf[j] = *(const uint2*)&sB[buf][k8][wn * 8 + j][lane][0];
            #pragma unroll
            for (int i = 0; i < 2; i++)
                #pragma unroll
                for (int j = 0; j < 8; j++)
                    mma_tf32(acc[i][j], af[i], bf[j]);
        }
    };

    const int S = (FF + 15) / 16;    // 13
    loadA(0); loadB(0); storeS(0);
    __syncthreads();
    for (int s = 0; s < S; s++) {
        if (s + 1 < S) { loadA((s + 1) * 16); loadB((s + 1) * 16); }
        compute(s & 1);
        if (s + 1 < S) storeS((s + 1) & 1);
        __syncthreads();
    }

    float* pjb = g_pjT + (size_t)b * EE * LP;
    #pragma unroll
    for (int i = 0; i < 2; i++) {
        int row = m0 + (wm * 2 + i) * 16 + (lane >> 2);
        #pragma unroll
        for (int j = 0; j < 8; j++) {
            int col = n0 + (wn * 8 + j) * 8 + (lane & 3) * 2;
            if (col < EE) {
                float b0 = bp[col], b1 = bp[col + 1];
                if (row < LP) {
                    pjb[(size_t)col * LP + row]       = tanhf(acc[i][j][0] + b0);
                    pjb[(size_t)(col + 1) * LP + row] = tanhf(acc[i][j][1] + b1);
                }
                if (row + 8 < LP) {
                    pjb[(size_t)col * LP + row + 8]       = tanhf(acc[i][j][2] + b0);
                    pjb[(size_t)(col + 1) * LP + row + 8] = tanhf(acc[i][j][3] + b1);
                }
            }
        }
    }
}

// ---------------- 5a. scores GEMM (tf32 mma): scores = avg @ pjT --------------
__global__ void __launch_bounds__(256) k_scores() {
    __shared__ __align__(16) unsigned sA[2][2][8][32][4];
    __shared__ __align__(16) unsigned sB[2][2][16][32][2];

    int b  = blockIdx.z;
    int m0 = blockIdx.x * 128;
    int n0 = blockIdx.y * 128;
    const float* Ap = g_avg;
    const float* Bp = g_pjT + (size_t)b * EE * LP;

    int t = threadIdx.x, lane = t & 31, wid = t >> 5;
    int wm = wid >> 1, wn = wid & 1;

    float acc[2][8][4];
    #pragma unroll
    for (int i = 0; i < 2; i++)
        #pragma unroll
        for (int j = 0; j < 8; j++)
            #pragma unroll
            for (int q = 0; q < 4; q++) acc[i][j][q] = 0.f;

    float ra[2][4];
    float rb[4][2];

    auto loadA = [&](int k0) {
        #pragma unroll
        for (int s = 0; s < 2; s++) {
            int slot = t + s * 256;
            int ls = slot & 31, tm = (slot >> 5) & 7, k8 = slot >> 8;
            int r = m0 + tm * 16 + (ls >> 2);
            int c = k0 + k8 * 8 + (ls & 3);
            bool rv0 = r < NLB, rv1 = (r + 8) < NLB;
            bool cv0 = c < EE,  cv1 = (c + 4) < EE;
            ra[s][0] = (rv0 && cv0) ? Ap[(size_t)r * EE + c]           : 0.f;
            ra[s][1] = (rv1 && cv0) ? Ap[(size_t)(r + 8) * EE + c]     : 0.f;
            ra[s][2] = (rv0 && cv1) ? Ap[(size_t)r * EE + c + 4]       : 0.f;
            ra[s][3] = (rv1 && cv1) ? Ap[(size_t)(r + 8) * EE + c + 4] : 0.f;
        }
    };
    auto loadB = [&](int k0) {
        #pragma unroll
        for (int s = 0; s < 4; s++) {
            int slot = t + s * 256;
            int ls = slot & 31, tn = (slot >> 5) & 15, k8 = slot >> 9;
            int k = k0 + k8 * 8 + (ls & 3);
            int l = n0 + tn * 8 + (ls >> 2);
            bool lv = l < LP;
            rb[s][0] = (k < EE && lv)       ? Bp[(size_t)k * LP + l]       : 0.f;
            rb[s][1] = ((k + 4) < EE && lv) ? Bp[(size_t)(k + 4) * LP + l] : 0.f;
        }
    };
    auto storeS = [&](int buf) {
        #pragma unroll
        for (int s = 0; s < 2; s++) {
            int slot = t + s * 256;
            int ls = slot & 31, tm = (slot >> 5) & 7, k8 = slot >> 8;
            unsigned* d = &sA[buf][k8][tm][ls][0];
            d[0] = cvt_tf32(ra[s][0]); d[1] = cvt_tf32(ra[s][1]);
            d[2] = cvt_tf32(ra[s][2]); d[3] = cvt_tf32(ra[s][3]);
        }
        #pragma unroll
        for (int s = 0; s < 4; s++) {
            int slot = t + s * 256;
            int ls = slot & 31, tn = (slot >> 5) & 15, k8 = slot >> 9;
            unsigned* d = &sB[buf][k8][tn][ls][0];
            d[0] = cvt_tf32(rb[s][0]); d[1] = cvt_tf32(rb[s][1]);
        }
    };
    auto compute = [&](int buf) {
        #pragma unroll
        for (int k8 = 0; k8 < 2; k8++) {
            unsigned af[2][4], bf[8][2];
            #pragma unroll
            for (int i = 0; i < 2; i++)
                *(uint4*)af[i] = *(const uint4*)&sA[buf][k8][wm * 2 + i][lane][0];
            #pragma unroll
            for (int j = 0; j < 8; j++)
                *(uint2*)bf[j] = *(const uint2*)&sB[buf][k8][wn * 8 + j][lane][0];
            #pragma unroll
            for (int i = 0; i < 2; i++)
                #pragma unroll
                for (int j = 0; j < 8; j++)
                    mma_tf32(acc[i][j], af[i], bf[j]);
        }
    };

    const int S = (EE + 15) / 16;   // 19 stages
    loadA(0); loadB(0); storeS(0);
    __syncthreads();
    for (int s = 0; s < S; s++) {
        if (s + 1 < S) { loadA((s + 1) * 16); loadB((s + 1) * 16); }
        compute(s & 1);
        if (s + 1 < S) storeS((s + 1) & 1);
        __syncthreads();
    }

    #pragma unroll
    for (int i = 0; i < 2; i++) {
        int row = m0 + (wm * 2 + i) * 16 + (lane >> 2);
        #pragma unroll
        for (int j = 0; j < 8; j++) {
            int col = n0 + (wn * 8 + j) * 8 + (lane & 3) * 2;
            size_t base = ((size_t)(b * NLB + row)) * LPAD + col;
            if (row < NLB) {
                float2 o0 = make_float2(acc[i][j][0], acc[i][j][1]);
                *(float2*)&g_scores[base] = o0;
            }
            if (row + 8 < NLB) {
                float2 o1 = make_float2(acc[i][j][2], acc[i][j][3]);
                *(float2*)&g_scores[base + (size_t)8 * LPAD] = o1;
            }
        }
    }
}

// ---------------- 5b. row softmax (exp + rowsum, in-place) --------------------
__global__ void __launch_bounds__(256) k_softmax() {
    int wid = threadIdx.x >> 5, lane = threadIdx.x & 31;
    int row = blockIdx.x * 8 + wid;            // row < BB*NLB
    float4* p = (float4*)(g_scores + (size_t)row * LPAD);
    float4 v[16];
    float m = -1e30f;
    #pragma unroll
    for (int q = 0; q < 16; q++) {
        v[q] = p[q * 32 + lane];
        int base = (q * 32 + lane) * 4;
        if (base + 0 < LP) m = fmaxf(m, v[q].x);
        if (base + 1 < LP) m = fmaxf(m, v[q].y);
        if (base + 2 < LP) m = fmaxf(m, v[q].z);
        if (base + 3 < LP) m = fmaxf(m, v[q].w);
    }
    #pragma unroll
    for (int o = 16; o; o >>= 1) m = fmaxf(m, __shfl_xor_sync(~0u, m, o));
    float s = 0.f;
    #pragma unroll
    for (int q = 0; q < 16; q++) {
        int base = (q * 32 + lane) * 4;
        v[q].x = (base + 0 < LP) ? expf(v[q].x - m) : 0.f;
        v[q].y = (base + 1 < LP) ? expf(v[q].y - m) : 0.f;
        v[q].z = (base + 2 < LP) ? expf(v[q].z - m) : 0.f;
        v[q].w = (base + 3 < LP) ? expf(v[q].w - m) : 0.f;
        s += v[q].x + v[q].y + v[q].z + v[q].w;
        p[q * 32 + lane] = v[q];
    }
    #pragma unroll
    for (int o = 16; o; o >>= 1) s += __shfl_xor_sync(~0u, s, o);
    if (lane == 0) g_rowsum[row] = s;
}

// ---------------- 5c. attn_out GEMM (tf32 mma): exp_scores @ c, /rowsum -------
__global__ void __launch_bounds__(256) k_attnout() {
    __shared__ __align__(16) unsigned sA[2][2][8][32][4];
    __shared__ __align__(16) unsigned sB[2][2][16][32][2];

    int b  = blockIdx.z;
    int m0 = blockIdx.x * 128;
    int n0 = blockIdx.y * 128;
    const float* Ap = g_scores + (size_t)b * NLB * LPAD;
    const float* Bp = g_c + (size_t)b * LP * FF;

    int t = threadIdx.x, lane = t & 31, wid = t >> 5;
    int wm = wid >> 1, wn = wid & 1;

    float acc[2][8][4];
    #pragma unroll
    for (int i = 0; i < 2; i++)
        #pragma unroll
        for (int j = 0; j < 8; j++)
            #pragma unroll
            for (int q = 0; q < 4; q++) acc[i][j][q] = 0.f;

    float ra[2][4];
    float rb[4][2];

    auto loadA = [&](int k0) {
        #pragma unroll
        for (int s = 0; s < 2; s++) {
            int slot = t + s * 256;
            int ls = slot & 31, tm = (slot >> 5) & 7, k8 = slot >> 8;
            int r = m0 + tm * 16 + (ls >> 2);
            int c = k0 + k8 * 8 + (ls & 3);
            bool rv0 = r < NLB, rv1 = (r + 8) < NLB;
            ra[s][0] = rv0 ? Ap[(size_t)r * LPAD + c]           : 0.f;
            ra[s][1] = rv1 ? Ap[(size_t)(r + 8) * LPAD + c]     : 0.f;
            ra[s][2] = rv0 ? Ap[(size_t)r * LPAD + c + 4]       : 0.f;
            ra[s][3] = rv1 ? Ap[(size_t)(r + 8) * LPAD + c + 4] : 0.f;
        }
    };
    auto loadB = [&](int k0) {
        #pragma unroll
        for (int s = 0; s < 4; s++) {
            int slot = t + s * 256;
            int ls = slot & 31, tn = (slot >> 5) & 15, k8 = slot >> 9;
            int k = k0 + k8 * 8 + (ls & 3);
            int n = n0 + tn * 8 + (ls >> 2);
            bool nv = n < FF;
            rb[s][0] = (k < LP && nv)       ? Bp[(size_t)k * FF + n]       : 0.f;
            rb[s][1] = ((k + 4) < LP && nv) ? Bp[(size_t)(k + 4) * FF + n] : 0.f;
        }
    };
    auto storeS = [&](int buf) {
        #pragma unroll
        for (int s = 0; s < 2; s++) {
            int slot = t + s * 256;
            int ls = slot & 31, tm = (slot >> 5) & 7, k8 = slot >> 8;
            unsigned* d = &sA[buf][k8][tm][ls][0];
            d[0] = cvt_tf32(ra[s][0]); d[1] = cvt_tf32(ra[s][1]);
            d[2] = cvt_tf32(ra[s][2]); d[3] = cvt_tf32(ra[s][3]);
        }
        #pragma unroll
        for (int s = 0; s < 4; s++) {
            int slot = t + s * 256;
            int ls = slot & 31, tn = (slot >> 5) & 15, k8 = slot >> 9;
            unsigned* d = &sB[buf][k8][tn][ls][0];
            d[0] = cvt_tf32(rb[s][0]); d[1] = cvt_tf32(rb[s][1]);
        }
    };
    auto compute = [&](int buf) {
        #pragma unroll
        for (int k8 = 0; k8 < 2; k8++) {
            unsigned af[2][4], bf[8][2];
            #pragma unroll
            for (int i = 0; i < 2; i++)
                *(uint4*)af[i] = *(const uint4*)&sA[buf][k8][wm * 2 + i][lane][0];
            #pragma unroll
            for (int j = 0; j < 8; j++)
                *(uint2*)bf[j] = *(const uint2*)&sB[buf][k8][wn * 8 + j][lane][0];
            #pragma unroll
            for (int i = 0; i < 2; i++)
                #pragma unroll
                for (int j = 0; j < 8; j++)
                    mma_tf32(acc[i][j], af[i], bf[j]);
        }
    };

    const int S = LPAD / 16;   // 128 stages
    loadA(0); loadB(0); storeS(0);
    __syncthreads();
    for (int s = 0; s < S; s++) {
        if (s + 1 < S) { loadA((s + 1) * 16); loadB((s + 1) * 16); }
        compute(s & 1);
        if (s + 1 < S) storeS((s + 1) & 1);
        __syncthreads();
    }

    int bNL = b * NLB;
    #pragma unroll
    for (int i = 0; i < 2; i++) {
        int row = m0 + (wm * 2 + i) * 16 + (lane >> 2);
        float inv0 = (row < NLB)     ? 1.f / g_rowsum[bNL + row]     : 0.f;
        float inv1 = (row + 8 < NLB) ? 1.f / g_rowsum[bNL + row + 8] : 0.f;
        #pragma unroll
        for (int j = 0; j < 8; j++) {
            int col = n0 + (wn * 8 + j) * 8 + (lane & 3) * 2;
            if (col < FF) {
                if (row < NLB) {
                    float2 o = make_float2(acc[i][j][0] * inv0, acc[i][j][1] * inv0);
                    *(float2*)&g_ao[((size_t)(bNL + row)) * FF + col] = o;
                }
                if (row + 8 < NLB) {
                    float2 o = make_float2(acc[i][j][2] * inv1, acc[i][j][3] * inv1);
                    *(float2*)&g_ao[((size_t)(bNL + row + 8)) * FF + col] = o;
                }
            }
        }
    }
}

// ---------------- 5d. proj GEMM (tf32) fused with gemb dot -> logits ----------
__global__ void __launch_bounds__(256) k_projg(const float* __restrict__ Wo,
                                               const float* __restrict__ bo,
                                               float* __restrict__ out) {
    __shared__ __align__(16) unsigned sA[2][2][8][32][4];
    __shared__ __align__(16) unsigned sB[2][2][16][32][2];
    __shared__ float sred[256];

    int b  = blockIdx.y;
    int m0 = blockIdx.x * 128;
    const float* Ap = g_ao + (size_t)b * NLB * FF;

    int t = threadIdx.x, lane = t & 31, wid = t >> 5;
    int wm = wid >> 1, wn = wid & 1;

    float part[2][2] = {{0.f, 0.f}, {0.f, 0.f}};   // [i][row / row+8]
    float ra[2][4];
    float rb[4][2];
    float acc[2][8][4];

    auto loadA = [&](int k0) {
        #pragma unroll
        for (int s = 0; s < 2; s++) {
            int slot = t + s * 256;
            int ls = slot & 31, tm = (slot >> 5) & 7, k8 = slot >> 8;
            int r = m0 + tm * 16 + (ls >> 2);
            int c = k0 + k8 * 8 + (ls & 3);
            bool rv0 = r < NLB, rv1 = (r + 8) < NLB;
            bool cv0 = c < FF, cv1 = (c + 4) < FF;
            ra[s][0] = (rv0 && cv0) ? Ap[(size_t)r * FF + c]           : 0.f;
            ra[s][1] = (rv1 && cv0) ? Ap[(size_t)(r + 8) * FF + c]     : 0.f;
            ra[s][2] = (rv0 && cv1) ? Ap[(size_t)r * FF + c + 4]       : 0.f;
            ra[s][3] = (rv1 && cv1) ? Ap[(size_t)(r + 8) * FF + c + 4] : 0.f;
        }
    };
    auto loadB = [&](int k0, int n0) {
        #pragma unroll
        for (int s = 0; s < 4; s++) {
            int slot = t + s * 256;
            int ls = slot & 31, tn = (slot >> 5) & 15, k8 = slot >> 9;
            int k = k0 + k8 * 8 + (ls & 3);
            int n = n0 + tn * 8 + (ls >> 2);
            bool nv = n < FEAT;
            rb[s][0] = (k < FF && nv)       ? Wo[(size_t)k * FEAT + n]       : 0.f;
            rb[s][1] = ((k + 4) < FF && nv) ? Wo[(size_t)(k + 4) * FEAT + n] : 0.f;
        }
    };
    auto storeS = [&](int buf) {
        #pragma unroll
        for (int s = 0; s < 2; s++) {
            int slot = t + s * 256;
            int ls = slot & 31, tm = (slot >> 5) & 7, k8 = slot >> 8;
            unsigned* d = &sA[buf][k8][tm][ls][0];
            d[0] = cvt_tf32(ra[s][0]); d[1] = cvt_tf32(ra[s][1]);
            d[2] = cvt_tf32(ra[s][2]); d[3] = cvt_tf32(ra[s][3]);
        }
        #pragma unroll
        for (int s = 0; s < 4; s++) {
            int slot = t + s * 256;
            int ls = slot & 31, tn = (slot >> 5) & 15, k8 = slot >> 9;
            unsigned* d = &sB[buf][k8][tn][ls][0];
            d[0] = cvt_tf32(rb[s][0]); d[1] = cvt_tf32(rb[s][1]);
        }
    };
    auto compute = [&](int buf) {
        #pragma unroll
        for (int k8 = 0; k8 < 2; k8++) {
            unsigned af[2][4], bf[8][2];
            #pragma unroll
            for (int i = 0; i < 2; i++)
                *(uint4*)af[i] = *(const uint4*)&sA[buf][k8][wm * 2 + i][lane][0];
            #pragma unroll
            for (int j = 0; j < 8; j++)
                *(uint2*)bf[j] = *(const uint2*)&sB[buf][k8][wn * 8 + j][lane][0];
            #pragma unroll
            for (int i = 0; i < 2; i++)
                #pragma unroll
                for (int j = 0; j < 8; j++)
                    mma_tf32(acc[i][j], af[i], bf[j]);
        }
    };

    const int S = (FF + 15) / 16;    // 13
    for (int nt = 0; nt < 4; nt++) {
        int n0 = nt * 128;
        #pragma unroll
        for (int i = 0; i < 2; i++)
            #pragma unroll
            for (int j = 0; j < 8; j++)
                #pragma unroll
                for (int q = 0; q < 4; q++) acc[i][j][q] = 0.f;

        loadA(0); loadB(0, n0); storeS(0);
        __syncthreads();
        for (int s = 0; s < S; s++) {
            if (s + 1 < S) { loadA((s + 1) * 16); loadB((s + 1) * 16, n0); }
            compute(s & 1);
            if (s + 1 < S) storeS((s + 1) & 1);
            __syncthreads();
        }

        // fold: relu(acc + bo) * gemb into per-row partials
        #pragma unroll
        for (int i = 0; i < 2; i++) {
            int row = m0 + (wm * 2 + i) * 16 + (lane >> 2);
            const float* g0 = (row < NLB)     ? g_gemb + (size_t)row * FEAT       : g_gemb;
            const float* g1 = (row + 8 < NLB) ? g_gemb + (size_t)(row + 8) * FEAT : g_gemb;
            bool rv0 = row < NLB, rv1 = (row + 8) < NLB;
            #pragma unroll
            for (int j = 0; j < 8; j++) {
                int col = n0 + (wn * 8 + j) * 8 + (lane & 3) * 2;
                if (col < FEAT) {
                    float b0 = bo[col], b1 = bo[col + 1];
                    if (rv0)
                        part[i][0] += fmaxf(acc[i][j][0] + b0, 0.f) * g0[col]
                                    + fmaxf(acc[i][j][1] + b1, 0.f) * g0[col + 1];
                    if (rv1)
                        part[i][1] += fmaxf(acc[i][j][2] + b0, 0.f) * g1[col]
                                    + fmaxf(acc[i][j][3] + b1, 0.f) * g1[col + 1];
                }
            }
        }
        __syncthreads();
    }

    // reduce across quad lanes (cols), then across the 2 wn warps via smem
    #pragma unroll
    for (int i = 0; i < 2; i++) {
        #pragma unroll
        for (int h = 0; h < 2; h++) {
            float v = part[i][h];
            v += __shfl_xor_sync(~0u, v, 1);
            v += __shfl_xor_sync(~0u, v, 2);
            if ((lane & 3) == 0) {
                int rl = wm * 32 + i * 16 + (lane >> 2) + h * 8;
                sred[rl * 2 + wn] = v;
            }
        }
    }
    __syncthreads();
    if (t < 128) {
        int gn = m0 + t;
        if (gn < NLB)
            out[b * NLB + gn] = sred[t * 2] + sred[t * 2 + 1];
    }
}

// ---------------- 6. BCE loss (deterministic two-stage) -----------------------
__global__ void k_loss_part(const float* __restrict__ y, const float* __restrict__ logits) {
    __shared__ float red[256];
    float s = 0.f;
    for (int i = blockIdx.x * 256 + threadIdx.x; i < BB * NLB; i += 64 * 256) {
        float z = logits[i];
        float yy = y[i];
        s += fmaxf(z, 0.f) - z * yy + log1pf(expf(-fabsf(z)));
    }
    red[threadIdx.x] = s;
    __syncthreads();
    for (int o = 128; o; o >>= 1) {
        if (threadIdx.x < o) red[threadIdx.x] += red[threadIdx.x + o];
        __syncthreads();
    }
    if (threadIdx.x == 0) g_losspart[blockIdx.x] = red[0];
}

__global__ void k_loss_final(float* __restrict__ out) {
    if (threadIdx.x == 0) {
        float s = 0.f;
        for (int i = 0; i < 64; i++) s += g_losspart[i];
        out[BB * NLB] = s / (float)BB;
    }
}

// ---------------- launch -------------------------------------------------------
extern "C" void kernel_launch(void* const* d_in, const int* in_sizes, int n_in,
                              void* d_out, int out_size) {
    const int*   x     = (const int*)d_in[0];
    const float* y     = (const float*)d_in[1];
    const float* mask  = (const float*)d_in[2];
    const float* we    = (const float*)d_in[3];
    const int*   lidx  = (const int*)d_in[4];
    const float* lmask = (const float*)d_in[5];
    const float* adj   = (const float*)d_in[6];
    const float* nn    = (const float*)d_in[7];
    const float* Wg    = (const float*)d_in[8];
    const float* bg    = (const float*)d_in[9];
    const float* Wc    = (const float*)d_in[10];
    const float* bc    = (const float*)d_in[11];
    const float* Wp    = (const float*)d_in[12];
    const float* bp    = (const float*)d_in[13];
    const float* Wo    = (const float*)d_in[14];
    const float* bo    = (const float*)d_in[15];
    float* out = (float*)d_out;

    k_avg<<<NLB, 320>>>(we, lidx, lmask);
    k_graph<<<NLB, 320>>>(adj, nn, Wg, bg);

    dim3 ge((LL + 127) / 128, BB);
    k_embT<<<ge, 256>>>(x, mask, we);
    k_wct<<<(CKK * FF + 255) / 256, 256>>>(Wc);

    dim3 gv((LP + 127) / 128, 2, BB);        // 16 x 2 x 8
    k_convg<<<gv, 256>>>(bc);

    dim3 gj((LP + 127) / 128, 3, BB);        // 16 x 3 x 8
    k_pjg<<<gj, 256>>>(Wp, bp);

    dim3 gs((NLB + 127) / 128, LPAD / 128, BB);      // 70 x 16 x 8
    k_scores<<<gs, 256>>>();

    k_softmax<<<(BB * NLB) / 8, 256>>>();

    dim3 go((NLB + 127) / 128, (FF + 127) / 128, BB); // 70 x 2 x 8
    k_attnout<<<go, 256>>>();

    dim3 gp((NLB + 127) / 128, BB);          // 70 x 8
    k_projg<<<gp, 256>>>(Wo, bo, out);

    k_loss_part<<<64, 256>>>(y, out);
    k_loss_final<<<1, 32>>>(out);
}